// round 5
// baseline (speedup 1.0000x reference)
#include <cuda_runtime.h>
#include <cuda_fp16.h>

#define B   128
#define H0  224
#define W0  224
#define C1  16
#define HP  56          // pooled H/W after conv1(stride2)+maxpool2
#define C2  32
#define H2  28
#define W2  28
#define BN_EPS 1e-5f

#define NPIX1 ((double)B * 112.0 * 112.0)   // BN1 population (pre-pool y1)
#define NPIX2 ((double)B * H2 * W2)

// ---------------- scratch ----------------
__device__ __half  g_u1[B * HP * HP * C1];     // NHWC pooled conv1 raw, fp16
__device__ __half  g_y2[B * H2 * W2 * C2];     // NHWC conv2 raw, fp16
__device__ double  g_part1[32][C1][2];
__device__ double  g_part2[16][C2][2];
__device__ float   g_logit[B];

// ---------------- f32x2 helpers ----------------
__device__ __forceinline__ unsigned long long pk2(float lo, float hi) {
    unsigned long long r;
    asm("mov.b64 %0, {%1, %2};" : "=l"(r) : "f"(lo), "f"(hi));
    return r;
}
__device__ __forceinline__ void upk2(unsigned long long v, float& lo, float& hi) {
    asm("mov.b64 {%0, %1}, %2;" : "=f"(lo), "=f"(hi) : "l"(v));
}
#define FMA2(acc, a, b) asm("fma.rn.f32x2 %0, %1, %2, %0;" : "+l"(acc) : "l"(a), "l"(b))

__device__ __forceinline__ void u4_to_f8(uint4 u, float* f) {
    float2 a;
    a = __half22float2(*reinterpret_cast<__half2*>(&u.x)); f[0] = a.x; f[1] = a.y;
    a = __half22float2(*reinterpret_cast<__half2*>(&u.y)); f[2] = a.x; f[3] = a.y;
    a = __half22float2(*reinterpret_cast<__half2*>(&u.z)); f[4] = a.x; f[5] = a.y;
    a = __half22float2(*reinterpret_cast<__half2*>(&u.w)); f[6] = a.x; f[7] = a.y;
}

// 16-lane same-parity warp reduce (xor 16,8,4,2 keeps bit0 = channel-half)
__device__ __forceinline__ float hred(float v) {
    v += __shfl_xor_sync(0xffffffffu, v, 16);
    v += __shfl_xor_sync(0xffffffffu, v, 8);
    v += __shfl_xor_sync(0xffffffffu, v, 4);
    v += __shfl_xor_sync(0xffffffffu, v, 2);
    return v;
}

// ---------------- kernels ----------------
__global__ void k_zero() {
    double* p1 = &g_part1[0][0][0];
    double* p2 = &g_part2[0][0][0];
    for (int i = threadIdx.x; i < 32 * C1 * 2; i += blockDim.x) p1[i] = 0.0;
    for (int i = threadIdx.x; i < 16 * C2 * 2; i += blockDim.x) p2[i] = 0.0;
    if (threadIdx.x < B) g_logit[threadIdx.x] = 0.f;
}

// conv1(stride2,pad1; bias cancels in BN) + 2x2 maxpool + BN1 stats.
// Thread = (pooled pixel, channel-half): 8 channels, pixels packed in f32x2.
__global__ void __launch_bounds__(256) k_conv1pool(const float* __restrict__ x,
                                                   const float* __restrict__ w) {
    __shared__ unsigned long long ws2[27 * C1];   // [k27][c] (w,w) pairs
    __shared__ float sh_s[C1], sh_q[C1];
    for (int idx = threadIdx.x; idx < 27 * C1; idx += blockDim.x) {
        int c = idx & 15, k27 = idx >> 4;
        float wv = w[c * 27 + k27];
        ws2[idx] = pk2(wv, wv);
    }
    if (threadIdx.x < C1) { sh_s[threadIdx.x] = 0.f; sh_q[threadIdx.x] = 0.f; }
    __syncthreads();

    int t    = blockIdx.x * blockDim.x + threadIdx.x;   // exact: B*56*56*2
    int half = t & 1;                                   // lane parity == half
    int r    = t >> 1;
    int j = r % HP;
    int i = (r / HP) % HP;
    int n = r / (HP * HP);

    unsigned long long acc01[8], acc23[8];
#pragma unroll
    for (int c = 0; c < 8; c++) { acc01[c] = 0ull; acc23[c] = 0ull; }

    const int rb = 4 * i - 1;
    const int cb = 4 * j - 1;

    float patch[5][5];
#pragma unroll 1
    for (int ic = 0; ic < 3; ic++) {
        const float* base = x + ((n * 3 + ic) * H0) * W0;
#pragma unroll
        for (int rr = 0; rr < 5; rr++) {
            int row = rb + rr;
            if (row < 0) {
#pragma unroll
                for (int cc = 0; cc < 5; cc++) patch[rr][cc] = 0.f;
            } else {
                const float* xr = base + row * W0;
                patch[rr][0] = (cb >= 0) ? __ldg(xr + cb) : 0.f;
                float4 v4 = *reinterpret_cast<const float4*>(xr + cb + 1);
                patch[rr][1] = v4.x; patch[rr][2] = v4.y;
                patch[rr][3] = v4.z; patch[rr][4] = v4.w;
            }
        }
#pragma unroll
        for (int ky = 0; ky < 3; ky++) {
#pragma unroll
            for (int kx = 0; kx < 3; kx++) {
                unsigned long long v01 = pk2(patch[ky][kx],     patch[ky][kx + 2]);
                unsigned long long v23 = pk2(patch[ky + 2][kx], patch[ky + 2][kx + 2]);
                const unsigned long long* wrow = &ws2[(ic * 9 + ky * 3 + kx) * C1 + half * 8];
#pragma unroll
                for (int c = 0; c < 8; c++) {
                    unsigned long long wv = wrow[c];
                    FMA2(acc01[c], v01, wv);
                    FMA2(acc23[c], v23, wv);
                }
            }
        }
    }

    __half hmax[8];
#pragma unroll
    for (int c = 0; c < 8; c++) {
        float a0, a1, a2, a3;
        upk2(acc01[c], a0, a1);
        upk2(acc23[c], a2, a3);
        hmax[c] = __float2half(fmaxf(fmaxf(a0, a1), fmaxf(a2, a3)));
        float s = hred((a0 + a1) + (a2 + a3));
        float q = hred(fmaf(a0, a0, fmaf(a1, a1, fmaf(a2, a2, a3 * a3))));
        if ((threadIdx.x & 31) < 2) {        // lane 0 -> half 0, lane 1 -> half 1
            atomicAdd(&sh_s[half * 8 + c], s);
            atomicAdd(&sh_q[half * 8 + c], q);
        }
    }
    *reinterpret_cast<uint4*>(g_u1 + ((n * HP + i) * HP + j) * C1 + half * 8) =
        *reinterpret_cast<uint4*>(&hmax[0]);

    __syncthreads();
    if (threadIdx.x < C1) {
        int bin = blockIdx.x & 31;
        atomicAdd(&g_part1[bin][threadIdx.x][0], (double)sh_s[threadIdx.x]);
        atomicAdd(&g_part1[bin][threadIdx.x][1], (double)sh_q[threadIdx.x]);
    }
}

// conv2(stride2,pad1) + inline BN1+ReLU + BN2 stats. Thread = (pixel, c2-half):
// 8 c2 pairs = 16 output channels.
__global__ void __launch_bounds__(256) k_conv2(const float* __restrict__ w,
                                               const float* __restrict__ g1,
                                               const float* __restrict__ b1) {
    __shared__ unsigned long long ws2[9 * C1 * 16];   // [tap][ic][c2pair]
    __shared__ float sc1[C1], sh1[C1];
    __shared__ float s2s[C2], s2q[C2];
    for (int idx = threadIdx.x; idx < 9 * C1 * 16; idx += blockDim.x) {
        int c2p = idx & 15;
        int ic  = (idx >> 4) & 15;
        int q   = idx >> 8;
        ws2[idx] = pk2(w[(2 * c2p) * 144 + ic * 9 + q],
                       w[(2 * c2p + 1) * 144 + ic * 9 + q]);
    }
    if (threadIdx.x < C1) {
        int c = threadIdx.x;
        double s = 0.0, q = 0.0;
#pragma unroll
        for (int bb = 0; bb < 32; bb++) { s += g_part1[bb][c][0]; q += g_part1[bb][c][1]; }
        double mean = s / NPIX1;
        double var  = q / NPIX1 - mean * mean;
        float scale = g1[c] * (1.0f / sqrtf((float)var + BN_EPS));
        sc1[c] = scale;
        sh1[c] = b1[c] - (float)mean * scale;
    }
    if (threadIdx.x < C2) { s2s[threadIdx.x] = 0.f; s2q[threadIdx.x] = 0.f; }
    __syncthreads();

    int t    = blockIdx.x * blockDim.x + threadIdx.x;   // exact: B*28*28*2
    int half = t & 1;
    int r    = t >> 1;
    int wo = r % W2;
    int ho = (r / W2) % H2;
    int n  = r / (W2 * H2);

    unsigned long long acc[8];
#pragma unroll
    for (int p = 0; p < 8; p++) acc[p] = 0ull;

#pragma unroll
    for (int ky = 0; ky < 3; ky++) {
        int row = 2 * ho - 1 + ky;
        bool rok = (row >= 0);
#pragma unroll
        for (int kx = 0; kx < 3; kx++) {
            int col = 2 * wo - 1 + kx;
            if (!rok || col < 0) continue;           // zero padding contributes 0
            const uint4* p4 = reinterpret_cast<const uint4*>(
                g_u1 + ((n * HP + row) * HP + col) * C1);
            float f[16];
            u4_to_f8(p4[0], f);
            u4_to_f8(p4[1], f + 8);
            const unsigned long long* wq = &ws2[(ky * 3 + kx) * C1 * 16 + half * 8];
#pragma unroll
            for (int ic = 0; ic < C1; ic++) {
                float h = fmaxf(fmaf(sc1[ic], f[ic], sh1[ic]), 0.f);
                unsigned long long vv = pk2(h, h);
#pragma unroll
                for (int p = 0; p < 8; p++)
                    FMA2(acc[p], vv, wq[ic * 16 + p]);
            }
        }
    }

    // NHWC store (16 halves = 32B) + BN2 stats for this half's 16 channels
    __half hout[16];
#pragma unroll
    for (int p = 0; p < 8; p++) {
        float f0, f1;
        upk2(acc[p], f0, f1);
        hout[2 * p]     = __float2half(f0);
        hout[2 * p + 1] = __float2half(f1);
        float s0 = hred(f0), q0 = hred(f0 * f0);
        float s1 = hred(f1), q1 = hred(f1 * f1);
        if ((threadIdx.x & 31) < 2) {
            int c = half * 16 + 2 * p;
            atomicAdd(&s2s[c], s0);     atomicAdd(&s2q[c], q0);
            atomicAdd(&s2s[c + 1], s1); atomicAdd(&s2q[c + 1], q1);
        }
    }
    uint4* yp = reinterpret_cast<uint4*>(g_y2 + ((n * H2 + ho) * W2 + wo) * C2 + half * 16);
    yp[0] = *reinterpret_cast<uint4*>(&hout[0]);
    yp[1] = *reinterpret_cast<uint4*>(&hout[8]);

    __syncthreads();
    if (threadIdx.x < C2) {
        int bin = blockIdx.x & 15;
        atomicAdd(&g_part2[bin][threadIdx.x][0], (double)s2s[threadIdx.x]);
        atomicAdd(&g_part2[bin][threadIdx.x][1], (double)s2q[threadIdx.x]);
    }
}

// BN2+ReLU+avg+fc partial sums: 8 blocks per sample -> atomic into g_logit
__global__ void __launch_bounds__(256) k_final2(const float* __restrict__ g2,
                                                const float* __restrict__ b2,
                                                const float* __restrict__ fcw) {
    __shared__ float ssc[C2], ssh[C2], sw[C2];
    __shared__ float red[256];
    int tid = threadIdx.x;
    if (tid < C2) {
        double s = 0.0, q = 0.0;
#pragma unroll
        for (int bb = 0; bb < 16; bb++) { s += g_part2[bb][tid][0]; q += g_part2[bb][tid][1]; }
        double mean = s / NPIX2;
        double var  = q / NPIX2 - mean * mean;
        float scale = g2[tid] * (1.0f / sqrtf((float)var + BN_EPS));
        ssc[tid] = scale;
        ssh[tid] = b2[tid] - (float)mean * scale;
        sw[tid]  = fcw[tid];
    }
    __syncthreads();

    int cg = (tid & 3) * 8;     // channel group invariant at stride 256
    float rsc[8], rsh[8], rw[8];
#pragma unroll
    for (int k = 0; k < 8; k++) { rsc[k] = ssc[cg + k]; rsh[k] = ssh[cg + k]; rw[k] = sw[cg + k]; }

    int n     = blockIdx.x >> 3;
    int chunk = blockIdx.x & 7;
    const uint4* p = reinterpret_cast<const uint4*>(g_y2 + n * H2 * W2 * C2);
    const int NV = H2 * W2 * C2 / 8;          // 3136 uint4 per sample
    int start = chunk * (NV / 8);             // 392 per chunk
    float acc = 0.f;
    for (int i = start + tid; i < start + NV / 8; i += 256) {
        float f[8];
        u4_to_f8(p[i], f);
#pragma unroll
        for (int k = 0; k < 8; k++) {
            float e = fmaxf(fmaf(rsc[k], f[k], rsh[k]), 0.f);
            acc = fmaf(rw[k], e, acc);
        }
    }
    red[tid] = acc;
    __syncthreads();
    for (int o = 128; o > 0; o >>= 1) {
        if (tid < o) red[tid] += red[tid + o];
        __syncthreads();
    }
    if (tid == 0) atomicAdd(&g_logit[n], red[0]);
}

__global__ void k_cos(const float* __restrict__ fcb, float* __restrict__ out) {
    int n = threadIdx.x;
    if (n < B) {
        float logit = g_logit[n] / (float)(H2 * W2) + fcb[0];
        float pr = cosf(logit);
        out[2 * n]     = pr;
        out[2 * n + 1] = 1.f - pr;
    }
}

// ---------------- launcher ----------------
extern "C" void kernel_launch(void* const* d_in, const int* in_sizes, int n_in,
                              void* d_out, int out_size) {
    const float* x    = (const float*)d_in[0];
    const float* c1w  = (const float*)d_in[1];
    const float* bn1g = (const float*)d_in[3];
    const float* bn1b = (const float*)d_in[4];
    const float* c2w  = (const float*)d_in[5];
    const float* bn2g = (const float*)d_in[7];
    const float* bn2b = (const float*)d_in[8];
    const float* fcw  = (const float*)d_in[9];
    const float* fcb  = (const float*)d_in[10];
    float* out = (float*)d_out;

    k_zero<<<1, 256>>>();
    k_conv1pool<<<(B * HP * HP * 2) / 256, 256>>>(x, c1w);   // 3136 blocks
    k_conv2<<<(B * H2 * W2 * 2) / 256, 256>>>(c2w, bn1g, bn1b); // 784 blocks
    k_final2<<<B * 8, 256>>>(bn2g, bn2b, fcw);
    k_cos<<<1, 128>>>(fcb, out);
}

// round 6
// speedup vs baseline: 1.1639x; 1.1639x over previous
#include <cuda_runtime.h>
#include <cuda_fp16.h>

#define B   128
#define H0  224
#define W0  224
#define C1  16
#define HP  56          // pooled H/W after conv1(stride2)+maxpool2
#define C2  32
#define H2  28
#define W2  28
#define BN_EPS 1e-5f

#define NPIX1 ((double)B * 112.0 * 112.0)
#define NPIX2 ((double)B * H2 * W2)

// ---------------- scratch ----------------
__device__ __half  g_u1[B * HP * HP * C1];     // NHWC pooled conv1 raw, fp16
__device__ __half  g_y2[B * H2 * W2 * C2];     // NHWC conv2 raw, fp16
__device__ double  g_part1[32][C1][2];
__device__ double  g_part2[16][C2][2];
__device__ float   g_logit[B];

// ---------------- f32x2 helpers ----------------
__device__ __forceinline__ unsigned long long pk2(float lo, float hi) {
    unsigned long long r;
    asm("mov.b64 %0, {%1, %2};" : "=l"(r) : "f"(lo), "f"(hi));
    return r;
}
__device__ __forceinline__ void upk2(unsigned long long v, float& lo, float& hi) {
    asm("mov.b64 {%0, %1}, %2;" : "=f"(lo), "=f"(hi) : "l"(v));
}
#define FMA2(acc, a, b) asm("fma.rn.f32x2 %0, %1, %2, %0;" : "+l"(acc) : "l"(a), "l"(b))

__device__ __forceinline__ void u4_to_f8(uint4 u, float* f) {
    float2 a;
    a = __half22float2(*reinterpret_cast<__half2*>(&u.x)); f[0] = a.x; f[1] = a.y;
    a = __half22float2(*reinterpret_cast<__half2*>(&u.y)); f[2] = a.x; f[3] = a.y;
    a = __half22float2(*reinterpret_cast<__half2*>(&u.z)); f[4] = a.x; f[5] = a.y;
    a = __half22float2(*reinterpret_cast<__half2*>(&u.w)); f[6] = a.x; f[7] = a.y;
}

// 16-lane same-parity reduce (xor 16,8,4,2 preserves bit0 = channel-half)
__device__ __forceinline__ float hred(float v) {
    v += __shfl_xor_sync(0xffffffffu, v, 16);
    v += __shfl_xor_sync(0xffffffffu, v, 8);
    v += __shfl_xor_sync(0xffffffffu, v, 4);
    v += __shfl_xor_sync(0xffffffffu, v, 2);
    return v;
}

// ---------------- kernels ----------------
__global__ void k_zero() {
    double* p1 = &g_part1[0][0][0];
    double* p2 = &g_part2[0][0][0];
    for (int i = threadIdx.x; i < 32 * C1 * 2; i += blockDim.x) p1[i] = 0.0;
    for (int i = threadIdx.x; i < 16 * C2 * 2; i += blockDim.x) p2[i] = 0.0;
    if (threadIdx.x < B) g_logit[threadIdx.x] = 0.f;
}

// conv1(stride2,pad1; bias cancels in BN) + 2x2 maxpool + BN1 stats.
// Block = 128 thr = 8x8 pooled tile x 2 channel-halves. Input tile in smem.
// Tile: 3ch x 33rows x 36stride fp32; smem col 3 = global col 32*tj-1.
__global__ void __launch_bounds__(128) k_conv1pool(const float* __restrict__ x,
                                                   const float* __restrict__ w) {
    __shared__ float tile[3 * 33 * 36];
    __shared__ unsigned long long ws2[27 * C1];   // [tap][c] (w,w) pairs
    __shared__ float sh_s[C1], sh_q[C1];

    int tid = threadIdx.x;
    int blk = blockIdx.x;                 // n*49 + ti*7 + tj
    int tj  = blk % 7;
    int ti  = (blk / 7) % 7;
    int n   = blk / 49;

    for (int idx = tid; idx < 27 * C1; idx += 128) {
        int c = idx & 15, tap = idx >> 4;
        float wv = w[c * 27 + tap];
        ws2[idx] = pk2(wv, wv);
    }
    if (tid < C1) { sh_s[tid] = 0.f; sh_q[tid] = 0.f; }

    // cooperative input tile load: 99 row-tasks (3ch x 33rows)
    // float4 part: 99*8 = 792 tasks, 32 floats/row at cols 32*tj .. 32*tj+31
    const int rowg0 = 32 * ti - 1;
    for (int f = tid; f < 792; f += 128) {
        int quad = f & 7;
        int rt   = f >> 3;                // 0..98
        int ch   = rt / 33;
        int rr   = rt - ch * 33;
        int rg   = rowg0 + rr;
        float4 v = make_float4(0.f, 0.f, 0.f, 0.f);
        if (rg >= 0)
            v = *reinterpret_cast<const float4*>(
                x + ((n * 3 + ch) * H0 + rg) * W0 + 32 * tj + 4 * quad);
        *reinterpret_cast<float4*>(&tile[ch * 1188 + rr * 36 + 4 + 4 * quad]) = v;
    }
    // scalar part: leftmost col (global 32*tj-1) -> smem col 3
    if (tid < 99) {
        int ch = tid / 33;
        int rr = tid - ch * 33;
        int rg = rowg0 + rr;
        int cg = 32 * tj - 1;
        float v = 0.f;
        if (rg >= 0 && cg >= 0) v = x[((n * 3 + ch) * H0 + rg) * W0 + cg];
        tile[ch * 1188 + rr * 36 + 3] = v;
    }
    __syncthreads();

    int half = tid & 1;
    int p    = tid >> 1;                  // 0..63
    int pj   = p & 7;
    int pi   = p >> 3;
    int i    = ti * 8 + pi;               // pooled coords
    int j    = tj * 8 + pj;

    unsigned long long acc01[8], acc23[8];
#pragma unroll
    for (int c = 0; c < 8; c++) { acc01[c] = 0ull; acc23[c] = 0ull; }

    float patch[5][5];
#pragma unroll 1
    for (int ic = 0; ic < 3; ic++) {
        const float* tb = &tile[ic * 1188 + (4 * pi) * 36 + 3 + 4 * pj];
#pragma unroll
        for (int r = 0; r < 5; r++)
#pragma unroll
            for (int c = 0; c < 5; c++)
                patch[r][c] = tb[r * 36 + c];
#pragma unroll
        for (int ky = 0; ky < 3; ky++) {
#pragma unroll
            for (int kx = 0; kx < 3; kx++) {
                unsigned long long v01 = pk2(patch[ky][kx],     patch[ky][kx + 2]);
                unsigned long long v23 = pk2(patch[ky + 2][kx], patch[ky + 2][kx + 2]);
                const unsigned long long* wrow = &ws2[(ic * 9 + ky * 3 + kx) * C1 + half * 8];
#pragma unroll
                for (int c = 0; c < 8; c++) {
                    unsigned long long wv = wrow[c];
                    FMA2(acc01[c], v01, wv);
                    FMA2(acc23[c], v23, wv);
                }
            }
        }
    }

    __half hmax[8];
#pragma unroll
    for (int c = 0; c < 8; c++) {
        float a0, a1, a2, a3;
        upk2(acc01[c], a0, a1);
        upk2(acc23[c], a2, a3);
        hmax[c] = __float2half(fmaxf(fmaxf(a0, a1), fmaxf(a2, a3)));
        float s = hred((a0 + a1) + (a2 + a3));
        float q = hred(fmaf(a0, a0, fmaf(a1, a1, fmaf(a2, a2, a3 * a3))));
        if ((tid & 31) < 2) {
            atomicAdd(&sh_s[half * 8 + c], s);
            atomicAdd(&sh_q[half * 8 + c], q);
        }
    }
    *reinterpret_cast<uint4*>(g_u1 + ((n * HP + i) * HP + j) * C1 + half * 8) =
        *reinterpret_cast<uint4*>(&hmax[0]);

    __syncthreads();
    if (tid < C1) {
        int bin = blk & 31;
        atomicAdd(&g_part1[bin][tid][0], (double)sh_s[tid]);
        atomicAdd(&g_part1[bin][tid][1], (double)sh_q[tid]);
    }
}

// conv2(stride2,pad1) + inline BN1+ReLU on NHWC loads, fused BN2 stats.
// One thread = one output pixel, all 32 channels (16 f32x2 pairs). (R4 form.)
__global__ void __launch_bounds__(256) k_conv2(const float* __restrict__ w,
                                               const float* __restrict__ g1,
                                               const float* __restrict__ b1) {
    __shared__ unsigned long long ws2[9 * C1 * 16];
    __shared__ float sc1[C1], sh1[C1];
    __shared__ float s2s[C2], s2q[C2];
    for (int idx = threadIdx.x; idx < 9 * C1 * 16; idx += blockDim.x) {
        int c2p = idx & 15;
        int ic  = (idx >> 4) & 15;
        int q   = idx >> 8;
        ws2[idx] = pk2(w[(2 * c2p) * 144 + ic * 9 + q],
                       w[(2 * c2p + 1) * 144 + ic * 9 + q]);
    }
    if (threadIdx.x < C1) {
        int c = threadIdx.x;
        double s = 0.0, q = 0.0;
#pragma unroll
        for (int bb = 0; bb < 32; bb++) { s += g_part1[bb][c][0]; q += g_part1[bb][c][1]; }
        double mean = s / NPIX1;
        double var  = q / NPIX1 - mean * mean;
        float scale = g1[c] * (1.0f / sqrtf((float)var + BN_EPS));
        sc1[c] = scale;
        sh1[c] = b1[c] - (float)mean * scale;
    }
    if (threadIdx.x < C2) { s2s[threadIdx.x] = 0.f; s2q[threadIdx.x] = 0.f; }
    __syncthreads();

    int t  = blockIdx.x * blockDim.x + threadIdx.x;   // exact: B*28*28
    int wo = t % W2;
    int ho = (t / W2) % H2;
    int n  = t / (W2 * H2);

    unsigned long long acc[16];
#pragma unroll
    for (int c2 = 0; c2 < 16; c2++) acc[c2] = 0ull;

#pragma unroll
    for (int ky = 0; ky < 3; ky++) {
        int row = 2 * ho - 1 + ky;
        bool rok = (row >= 0);
#pragma unroll
        for (int kx = 0; kx < 3; kx++) {
            int col = 2 * wo - 1 + kx;
            if (!rok || col < 0) continue;
            const uint4* p4 = reinterpret_cast<const uint4*>(
                g_u1 + ((n * HP + row) * HP + col) * C1);
            float f[16];
            u4_to_f8(p4[0], f);
            u4_to_f8(p4[1], f + 8);
            const unsigned long long* wq = &ws2[(ky * 3 + kx) * C1 * 16];
#pragma unroll
            for (int ic = 0; ic < C1; ic++) {
                float h = fmaxf(fmaf(sc1[ic], f[ic], sh1[ic]), 0.f);
                unsigned long long vv = pk2(h, h);
#pragma unroll
                for (int c2 = 0; c2 < 16; c2++)
                    FMA2(acc[c2], vv, wq[ic * 16 + c2]);
            }
        }
    }

    __half hout[C2];
#pragma unroll
    for (int c2 = 0; c2 < 16; c2++) {
        float f0, f1;
        upk2(acc[c2], f0, f1);
        hout[2 * c2]     = __float2half(f0);
        hout[2 * c2 + 1] = __float2half(f1);
        float s0 = f0, q0 = f0 * f0, s1 = f1, q1 = f1 * f1;
#pragma unroll
        for (int o = 16; o > 0; o >>= 1) {
            s0 += __shfl_xor_sync(0xffffffffu, s0, o);
            q0 += __shfl_xor_sync(0xffffffffu, q0, o);
            s1 += __shfl_xor_sync(0xffffffffu, s1, o);
            q1 += __shfl_xor_sync(0xffffffffu, q1, o);
        }
        if ((threadIdx.x & 31) == 0) {
            atomicAdd(&s2s[2 * c2], s0);     atomicAdd(&s2q[2 * c2], q0);
            atomicAdd(&s2s[2 * c2 + 1], s1); atomicAdd(&s2q[2 * c2 + 1], q1);
        }
    }
    uint4* yp = reinterpret_cast<uint4*>(g_y2 + ((n * H2 + ho) * W2 + wo) * C2);
#pragma unroll
    for (int k = 0; k < 4; k++) yp[k] = *reinterpret_cast<uint4*>(&hout[8 * k]);

    __syncthreads();
    if (threadIdx.x < C2) {
        int bin = blockIdx.x & 15;
        atomicAdd(&g_part2[bin][threadIdx.x][0], (double)s2s[threadIdx.x]);
        atomicAdd(&g_part2[bin][threadIdx.x][1], (double)s2q[threadIdx.x]);
    }
}

// BN2+ReLU+avg+fc partials: 2 blocks/sample -> atomic into g_logit
__global__ void __launch_bounds__(256) k_final2(const float* __restrict__ g2,
                                                const float* __restrict__ b2,
                                                const float* __restrict__ fcw) {
    __shared__ float ssc[C2], ssh[C2], sw[C2];
    __shared__ float red[256];
    int tid = threadIdx.x;
    if (tid < C2) {
        double s = 0.0, q = 0.0;
#pragma unroll
        for (int bb = 0; bb < 16; bb++) { s += g_part2[bb][tid][0]; q += g_part2[bb][tid][1]; }
        double mean = s / NPIX2;
        double var  = q / NPIX2 - mean * mean;
        float scale = g2[tid] * (1.0f / sqrtf((float)var + BN_EPS));
        ssc[tid] = scale;
        ssh[tid] = b2[tid] - (float)mean * scale;
        sw[tid]  = fcw[tid];
    }
    __syncthreads();

    int cg = (tid & 3) * 8;
    float rsc[8], rsh[8], rw[8];
#pragma unroll
    for (int k = 0; k < 8; k++) { rsc[k] = ssc[cg + k]; rsh[k] = ssh[cg + k]; rw[k] = sw[cg + k]; }

    int n     = blockIdx.x >> 1;
    int chunk = blockIdx.x & 1;
    const uint4* p = reinterpret_cast<const uint4*>(g_y2 + n * H2 * W2 * C2);
    const int NV = H2 * W2 * C2 / 8;          // 3136 uint4/sample, 2x1568
    int start = chunk * (NV / 2);
    float acc = 0.f;
    for (int i = start + tid; i < start + NV / 2; i += 256) {
        float f[8];
        u4_to_f8(p[i], f);
#pragma unroll
        for (int k = 0; k < 8; k++) {
            float e = fmaxf(fmaf(rsc[k], f[k], rsh[k]), 0.f);
            acc = fmaf(rw[k], e, acc);
        }
    }
    red[tid] = acc;
    __syncthreads();
    for (int o = 128; o > 0; o >>= 1) {
        if (tid < o) red[tid] += red[tid + o];
        __syncthreads();
    }
    if (tid == 0) atomicAdd(&g_logit[n], red[0]);
}

__global__ void k_cos(const float* __restrict__ fcb, float* __restrict__ out) {
    int n = threadIdx.x;
    if (n < B) {
        float logit = g_logit[n] / (float)(H2 * W2) + fcb[0];
        float pr = cosf(logit);
        out[2 * n]     = pr;
        out[2 * n + 1] = 1.f - pr;
    }
}

// ---------------- launcher ----------------
extern "C" void kernel_launch(void* const* d_in, const int* in_sizes, int n_in,
                              void* d_out, int out_size) {
    const float* x    = (const float*)d_in[0];
    const float* c1w  = (const float*)d_in[1];
    const float* bn1g = (const float*)d_in[3];
    const float* bn1b = (const float*)d_in[4];
    const float* c2w  = (const float*)d_in[5];
    const float* bn2g = (const float*)d_in[7];
    const float* bn2b = (const float*)d_in[8];
    const float* fcw  = (const float*)d_in[9];
    const float* fcb  = (const float*)d_in[10];
    float* out = (float*)d_out;

    k_zero<<<1, 256>>>();
    k_conv1pool<<<B * 49, 128>>>(x, c1w);                    // 6272 blocks
    k_conv2<<<(B * H2 * W2) / 256, 256>>>(c2w, bn1g, bn1b);  // 392 blocks
    k_final2<<<B * 2, 256>>>(bn2g, bn2b, fcw);
    k_cos<<<1, 128>>>(fcb, out);
}